// round 16
// baseline (speedup 1.0000x reference)
#include <cuda_runtime.h>
#include <cstdint>
#include <cstddef>

#define B_   16
#define CI_  32
#define HH   224
#define WW   224
#define CO_  32
#define OH_  222
#define OW_  222

// fp16 operands split per ci-half plane, rows contiguous for bulk copy.
// per pixel 8 words; word order [2t]=h_t, [2t+1]=h_{t+4} (frag pairs).
static __device__ __align__(16) unsigned g_xA[(size_t)B_ * HH * WW * 8];
static __device__ __align__(16) unsigned g_xB[(size_t)B_ * HH * WW * 8];
static __device__ __align__(16) unsigned g_wA[9 * CO_ * 8];
static __device__ __align__(16) unsigned g_wB[9 * CO_ * 8];

#define THREADS 256
#define XT 2
#define YT 56              // tile rows: oh0 = min(4*by, 218)
#define TROWS 6
#define TCOLS 130          // exact input span: px0 + 129 <= 223
#define SA_PLANE (TROWS * TCOLS * 8)        // 6240 words
#define SB_PLANE (9 * CO_ * 8)              // 2304 words
#define SMEM_WORDS (8 + 2 * SA_PLANE + 2 * SB_PLANE)   // 17096 (8 = 2 mbarriers)
#define SMEM_BYTES (SMEM_WORDS * 4)                    // 68384 -> 2 CTAs/SM
#define PLANE_TX (TROWS * TCOLS * 32 + 9 * CO_ * 32)   // 34176 bytes per plane

__device__ __forceinline__ unsigned pack_f16x2(float even, float odd) {
    unsigned d;
    asm("cvt.rn.f16x2.f32 %0, %1, %2;" : "=r"(d) : "f"(odd), "f"(even));
    return d;
}
__device__ __forceinline__ void mma_f16(float* c, unsigned a0, unsigned a1,
                                        unsigned a2, unsigned a3,
                                        unsigned b0, unsigned b1) {
    asm volatile(
        "mma.sync.aligned.m16n8k16.row.col.f32.f16.f16.f32 "
        "{%0,%1,%2,%3}, {%4,%5,%6,%7}, {%8,%9}, {%0,%1,%2,%3};"
        : "+f"(c[0]), "+f"(c[1]), "+f"(c[2]), "+f"(c[3])
        : "r"(a0), "r"(a1), "r"(a2), "r"(a3), "r"(b0), "r"(b1));
}
__device__ __forceinline__ void bulk_g2s(unsigned dst, const void* src,
                                         unsigned bytes, unsigned mbar) {
    asm volatile(
        "cp.async.bulk.shared::cluster.global.mbarrier::complete_tx::bytes "
        "[%0], [%1], %2, [%3];"
        :: "r"(dst), "l"(src), "r"(bytes), "r"(mbar) : "memory");
}
__device__ __forceinline__ void mbar_init(unsigned mbar, unsigned cnt) {
    asm volatile("mbarrier.init.shared.b64 [%0], %1;" :: "r"(mbar), "r"(cnt) : "memory");
}
__device__ __forceinline__ void mbar_expect_tx(unsigned mbar, unsigned bytes) {
    asm volatile("mbarrier.arrive.expect_tx.shared.b64 _, [%0], %1;"
                 :: "r"(mbar), "r"(bytes) : "memory");
}
__device__ __forceinline__ void mbar_wait(unsigned mbar, unsigned parity) {
    asm volatile(
        "{ .reg .pred P1;\n\t"
        "WL_%=: mbarrier.try_wait.parity.shared.b64 P1, [%0], %1;\n\t"
        "@P1 bra.uni WD_%=;\n\t"
        "bra.uni WL_%=;\n\t"
        "WD_%=: }"
        :: "r"(mbar), "r"(parity) : "memory");
}

// convert 32 strided floats -> two 8-word plane cells in fragment order
__device__ __forceinline__ void convert32_f16(const float* src, size_t stride,
                                              uint4* dA, uint4* dB) {
    unsigned h[16];
    #pragma unroll
    for (int p = 0; p < 16; ++p) {
        float e = __ldg(src + (size_t)(2 * p) * stride);
        float o = __ldg(src + (size_t)(2 * p + 1) * stride);
        h[p] = pack_f16x2(e, o);
    }
    dA[0] = make_uint4(h[0], h[4], h[1], h[5]);
    dA[1] = make_uint4(h[2], h[6], h[3], h[7]);
    dB[0] = make_uint4(h[8], h[12], h[9], h[13]);
    dB[1] = make_uint4(h[10], h[14], h[11], h[15]);
}

// ---- pre-pass ----
#define XBLOCKS ((B_ * HH * 7 * 32) / 256)     // 3136
__global__ void __launch_bounds__(256) cvt_xw(const float* __restrict__ x,
                                              const float* __restrict__ w) {
    if (blockIdx.x == XBLOCKS) {
        for (int r = threadIdx.x; r < 288; r += 256) {
            const int tap = r >> 5, co = r & 31;
            convert32_f16(w + co * 288 + tap, 9,
                          (uint4*)(g_wA + (size_t)r * 8),
                          (uint4*)(g_wB + (size_t)r * 8));
        }
        return;
    }
    const int lane = threadIdx.x & 31;
    const int W    = (blockIdx.x * 256 + threadIdx.x) >> 5;
    const int wb   = W % 7;
    const int h    = (W / 7) % HH;
    const int b    = W / (7 * HH);
    const int iw   = wb * 32 + lane;
    const size_t px = ((size_t)b * HH + h) * WW + iw;
    convert32_f16(x + (size_t)b * CI_ * HH * WW + (size_t)h * WW + iw, (size_t)HH * WW,
                  (uint4*)(g_xA + px * 8), (uint4*)(g_xB + px * 8));
}

// one ci-half plane: 9 taps x 4 mt x 4 nt = 144 fp16 MMAs per warp
__device__ __forceinline__ void compute_plane(const unsigned* __restrict__ sA,
                                              const unsigned* __restrict__ sB,
                                              float acc[4][4][4],
                                              int orow, int mq, int g, int t) {
    #pragma unroll
    for (int ky = 0; ky < 3; ++ky) {
        #pragma unroll
        for (int kx = 0; kx < 3; ++kx) {
            const unsigned* bp = sB + (((ky * 3 + kx) * 32) + g) * 8 + t * 2;
            uint2 bf[4];
            #pragma unroll
            for (int nt = 0; nt < 4; ++nt)
                bf[nt] = *(const uint2*)(bp + nt * 64);

            const unsigned* ap = sA + (((orow + ky) * TCOLS + mq * 64 + kx + g)) * 8 + t * 2;
            #pragma unroll
            for (int mt = 0; mt < 4; ++mt) {
                uint2 aL = *(const uint2*)(ap + mt * 128);          // pixel row g
                uint2 aH = *(const uint2*)(ap + mt * 128 + 64);     // pixel row g+8
                #pragma unroll
                for (int nt = 0; nt < 4; ++nt)
                    mma_f16(acc[mt][nt], aL.x, aH.x, aL.y, aH.y, bf[nt].x, bf[nt].y);
            }
        }
    }
}

// ---- main: bulk-copy loads (no per-chunk LDGSTS issue tax) ----
__global__ void __launch_bounds__(THREADS, 2)
conv3x3_mma(const float* __restrict__ bias, float* __restrict__ out) {
    extern __shared__ unsigned smw[];
    // [0..3] mbar0, [4..7] mbar1, then planes
    unsigned* sA0 = smw + 8;
    unsigned* sA1 = sA0 + SA_PLANE;
    unsigned* sB0 = sA1 + SA_PLANE;
    unsigned* sB1 = sB0 + SB_PLANE;
    const unsigned base = (unsigned)__cvta_generic_to_shared(smw);
    const unsigned mb0 = base, mb1 = base + 16;
    const unsigned aA0 = base + 8 * 4;
    const unsigned aA1 = aA0 + SA_PLANE * 4;
    const unsigned aB0 = aA1 + SA_PLANE * 4;
    const unsigned aB1 = aB0 + SB_PLANE * 4;

    const int tid = threadIdx.x;
    const int blk = blockIdx.x;
    const int bx  = blk & 1;
    const int by  = (blk >> 1) % YT;
    const int b   = blk / (2 * YT);
    const int px0 = bx ? 94 : 0;
    const int oh0 = (by < YT - 1) ? by * 4 : 218;   // clamp: rows always in range

    if (tid == 0) { mbar_init(mb0, 1); mbar_init(mb1, 1); }
    __syncthreads();

    if (tid == 0) {
        // plane 0
        mbar_expect_tx(mb0, PLANE_TX);
        #pragma unroll
        for (int trow = 0; trow < TROWS; ++trow)
            bulk_g2s(aA0 + (unsigned)(trow * TCOLS * 32),
                     g_xA + (((size_t)b * HH + oh0 + trow) * WW + px0) * 8,
                     TCOLS * 32, mb0);
        bulk_g2s(aB0, g_wA, 9 * CO_ * 32, mb0);
        // plane 1
        mbar_expect_tx(mb1, PLANE_TX);
        #pragma unroll
        for (int trow = 0; trow < TROWS; ++trow)
            bulk_g2s(aA1 + (unsigned)(trow * TCOLS * 32),
                     g_xB + (((size_t)b * HH + oh0 + trow) * WW + px0) * 8,
                     TCOLS * 32, mb1);
        bulk_g2s(aB1, g_wB, 9 * CO_ * 32, mb1);
    }

    const int lane = tid & 31;
    const int wid  = tid >> 5;
    const int g = lane >> 2, t = lane & 3;
    const int orow = wid & 3;
    const int mq   = wid >> 2;

    float acc[4][4][4];
    #pragma unroll
    for (int mt = 0; mt < 4; mt++)
        #pragma unroll
        for (int nt = 0; nt < 4; nt++)
            #pragma unroll
            for (int i = 0; i < 4; i++) acc[mt][nt][i] = 0.f;

    mbar_wait(mb0, 0);
    compute_plane(sA0, sB0, acc, orow, mq, g, t);

    mbar_wait(mb1, 0);
    compute_plane(sA1, sB1, acc, orow, mq, g, t);

    // ---- epilogue (no guards: oh0 clamped, oy <= 221)
    const int oy = oh0 + orow;
    #pragma unroll
    for (int nt = 0; nt < 4; ++nt) {
        const int co0 = nt * 8 + t * 2;
        const float bs0 = __ldg(&bias[co0]);
        const float bs1 = __ldg(&bias[co0 + 1]);
        float* o0 = out + (((size_t)b * CO_ + co0)     * OH_ + oy) * OW_;
        float* o1 = out + (((size_t)b * CO_ + co0 + 1) * OH_ + oy) * OW_;
        #pragma unroll
        for (int mt = 0; mt < 4; ++mt) {
            const int pl = px0 + mq * 64 + mt * 16 + g;
            o0[pl]     = acc[mt][nt][0] + bs0;
            o1[pl]     = acc[mt][nt][1] + bs1;
            o0[pl + 8] = acc[mt][nt][2] + bs0;
            o1[pl + 8] = acc[mt][nt][3] + bs1;
        }
    }
}

extern "C" void kernel_launch(void* const* d_in, const int* in_sizes, int n_in,
                              void* d_out, int out_size)
{
    const float* x    = (const float*)d_in[0];
    const float* w    = (const float*)d_in[1];
    const float* bias = (const float*)d_in[2];
    float* out        = (float*)d_out;

    cvt_xw<<<XBLOCKS + 1, 256>>>(x, w);

    cudaFuncSetAttribute(conv3x3_mma,
                         cudaFuncAttributeMaxDynamicSharedMemorySize, SMEM_BYTES);
    conv3x3_mma<<<B_ * YT * XT, THREADS, SMEM_BYTES>>>(bias, out);
}

// round 17
// speedup vs baseline: 1.2248x; 1.2248x over previous
#include <cuda_runtime.h>
#include <cstdint>
#include <cstddef>

#define B_   16
#define CI_  32
#define HH   224
#define WW   224
#define CO_  32
#define OH_  222
#define OW_  222

// x planes: per pixel 8 words per plane, frag order [2t]=h_t, [2t+1]=h_{t+4}
static __device__ __align__(16) unsigned g_xA[(size_t)B_ * HH * WW * 8];
static __device__ __align__(16) unsigned g_xB[(size_t)B_ * HH * WW * 8];
// w: per row (tap*32+co) 16 words: [pl*8 + 2t]=h_{pl*8+t}, [pl*8+2t+1]=h_{pl*8+t+4}
static __device__ __align__(16) unsigned g_w16[9 * CO_ * 16];

#define THREADS 256
#define XT 2
#define YT 56
#define TROWS 6
#define TCOLS 130                           // exact span: px0 + 129 <= 223
#define SA_PLANE (TROWS * TCOLS * 8)        // 6240 words
#define SMEM_WORDS (8 + 2 * SA_PLANE)       // 12488
#define SMEM_BYTES (SMEM_WORDS * 4)         // 49952
#define PLANE_TX (TROWS * TCOLS * 32)       // 24960 bytes

__device__ __forceinline__ unsigned pack_f16x2(float even, float odd) {
    unsigned d;
    asm("cvt.rn.f16x2.f32 %0, %1, %2;" : "=r"(d) : "f"(odd), "f"(even));
    return d;
}
__device__ __forceinline__ void mma_f16(float* c, unsigned a0, unsigned a1,
                                        unsigned a2, unsigned a3,
                                        unsigned b0, unsigned b1) {
    asm volatile(
        "mma.sync.aligned.m16n8k16.row.col.f32.f16.f16.f32 "
        "{%0,%1,%2,%3}, {%4,%5,%6,%7}, {%8,%9}, {%0,%1,%2,%3};"
        : "+f"(c[0]), "+f"(c[1]), "+f"(c[2]), "+f"(c[3])
        : "r"(a0), "r"(a1), "r"(a2), "r"(a3), "r"(b0), "r"(b1));
}
__device__ __forceinline__ void bulk_g2s(unsigned dst, const void* src,
                                         unsigned bytes, unsigned mbar) {
    asm volatile(
        "cp.async.bulk.shared::cluster.global.mbarrier::complete_tx::bytes "
        "[%0], [%1], %2, [%3];"
        :: "r"(dst), "l"(src), "r"(bytes), "r"(mbar) : "memory");
}
__device__ __forceinline__ void mbar_init(unsigned mbar, unsigned cnt) {
    asm volatile("mbarrier.init.shared.b64 [%0], %1;" :: "r"(mbar), "r"(cnt) : "memory");
}
__device__ __forceinline__ void mbar_expect_tx(unsigned mbar, unsigned bytes) {
    asm volatile("mbarrier.arrive.expect_tx.shared.b64 _, [%0], %1;"
                 :: "r"(mbar), "r"(bytes) : "memory");
}
// canonical suspend-hint acquire wait (no busy spin)
__device__ __forceinline__ void mbar_wait(unsigned mbar, unsigned parity) {
    asm volatile(
        "{ .reg .pred P1;\n\t"
        "WL_%=:\n\t"
        "mbarrier.try_wait.parity.acquire.cta.shared::cta.b64 P1, [%0], %1, 0x989680;\n\t"
        "@P1 bra.uni WD_%=;\n\t"
        "bra.uni WL_%=;\n\t"
        "WD_%=: }"
        :: "r"(mbar), "r"(parity) : "memory");
}

// ---- pre-pass: x vectorized (4 px / thread, float4 loads); w in tail block ----
#define XQUADS (B_ * HH * (WW / 4))          // 200704
#define XBLOCKS (XQUADS / 256)               // 784
__global__ void __launch_bounds__(256) cvt_xw(const float* __restrict__ x,
                                              const float* __restrict__ w) {
    if (blockIdx.x == XBLOCKS) {             // ---- weights
        for (int r = threadIdx.x; r < 288; r += 256) {
            const int tap = r >> 5, co = r & 31;
            unsigned h[16];
            #pragma unroll
            for (int p = 0; p < 16; ++p) {
                float e = __ldg(&w[co * 288 + (2 * p) * 9 + tap]);
                float o = __ldg(&w[co * 288 + (2 * p + 1) * 9 + tap]);
                h[p] = pack_f16x2(e, o);
            }
            uint4* d4 = (uint4*)(g_w16 + (size_t)r * 16);
            d4[0] = make_uint4(h[0], h[4],  h[1], h[5]);
            d4[1] = make_uint4(h[2], h[6],  h[3], h[7]);
            d4[2] = make_uint4(h[8], h[12], h[9], h[13]);
            d4[3] = make_uint4(h[10], h[14], h[11], h[15]);
        }
        return;
    }
    const int id = blockIdx.x * 256 + threadIdx.x;
    const int w4 = id % 56;
    const int h_ = (id / 56) % HH;
    const int b  = id / (56 * HH);
    const int w0 = w4 * 4;
    const size_t pixbase = ((size_t)b * HH + h_) * WW + w0;

    #pragma unroll
    for (int pl = 0; pl < 2; ++pl) {
        float4 v[16];
        #pragma unroll
        for (int j = 0; j < 16; ++j)
            v[j] = __ldg((const float4*)(x + (((size_t)b * CI_ + pl * 16 + j) * HH + h_) * WW + w0));
        unsigned* dst = (pl ? g_xB : g_xA) + pixbase * 8;
        #pragma unroll
        for (int px = 0; px < 4; ++px) {
            const float* f = &v[0].x;         // v is contiguous float4 array
            unsigned h[8];
            #pragma unroll
            for (int p = 0; p < 8; ++p) {
                float e = (&v[2 * p].x)[px];
                float o = (&v[2 * p + 1].x)[px];
                h[p] = pack_f16x2(e, o);
            }
            (void)f;
            uint4* d4 = (uint4*)(dst + (size_t)px * 8);
            d4[0] = make_uint4(h[0], h[4], h[1], h[5]);
            d4[1] = make_uint4(h[2], h[6], h[3], h[7]);
        }
    }
}

// one ci-half plane: 9 taps x 4 mt x 4 nt = 144 fp16 MMAs/warp; B direct from gmem
__device__ __forceinline__ void compute_plane(const unsigned* __restrict__ sA,
                                              const unsigned* __restrict__ gB,
                                              float acc[4][4][4],
                                              int orow, int mq, int g, int t) {
    #pragma unroll
    for (int ky = 0; ky < 3; ++ky) {
        #pragma unroll
        for (int kx = 0; kx < 3; ++kx) {
            uint2 bf[4];
            #pragma unroll
            for (int nt = 0; nt < 4; ++nt)
                bf[nt] = __ldg((const uint2*)(gB + ((size_t)((ky * 3 + kx) * 32 + nt * 8 + g)) * 16 + t * 2));

            const unsigned* ap = sA + (((orow + ky) * TCOLS + mq * 64 + kx + g)) * 8 + t * 2;
            #pragma unroll
            for (int mt = 0; mt < 4; ++mt) {
                uint2 aL = *(const uint2*)(ap + mt * 128);
                uint2 aH = *(const uint2*)(ap + mt * 128 + 64);
                #pragma unroll
                for (int nt = 0; nt < 4; ++nt)
                    mma_f16(acc[mt][nt], aL.x, aH.x, aL.y, aH.y, bf[nt].x, bf[nt].y);
            }
        }
    }
}

// ---- main: A via bulk copy, B via gmem LDG ----
__global__ void __launch_bounds__(THREADS, 2)
conv3x3_mma(const float* __restrict__ bias, float* __restrict__ out) {
    extern __shared__ unsigned smw[];
    unsigned* sA0 = smw + 8;
    unsigned* sA1 = sA0 + SA_PLANE;
    const unsigned base = (unsigned)__cvta_generic_to_shared(smw);
    const unsigned mb0 = base, mb1 = base + 16;
    const unsigned aA0 = base + 32;
    const unsigned aA1 = aA0 + SA_PLANE * 4;

    const int tid = threadIdx.x;
    const int blk = blockIdx.x;
    const int bx  = blk & 1;
    const int by  = (blk >> 1) % YT;
    const int b   = blk / (2 * YT);
    const int px0 = bx ? 94 : 0;
    const int oh0 = (by < YT - 1) ? by * 4 : 218;

    if (tid == 0) { mbar_init(mb0, 1); mbar_init(mb1, 1); }
    __syncthreads();

    if (tid == 0) {
        mbar_expect_tx(mb0, PLANE_TX);
        #pragma unroll
        for (int trow = 0; trow < TROWS; ++trow)
            bulk_g2s(aA0 + (unsigned)(trow * TCOLS * 32),
                     g_xA + (((size_t)b * HH + oh0 + trow) * WW + px0) * 8,
                     TCOLS * 32, mb0);
        mbar_expect_tx(mb1, PLANE_TX);
        #pragma unroll
        for (int trow = 0; trow < TROWS; ++trow)
            bulk_g2s(aA1 + (unsigned)(trow * TCOLS * 32),
                     g_xB + (((size_t)b * HH + oh0 + trow) * WW + px0) * 8,
                     TCOLS * 32, mb1);
    }

    const int lane = tid & 31;
    const int wid  = tid >> 5;
    const int g = lane >> 2, t = lane & 3;
    const int orow = wid & 3;
    const int mq   = wid >> 2;

    float acc[4][4][4];
    #pragma unroll
    for (int mt = 0; mt < 4; mt++)
        #pragma unroll
        for (int nt = 0; nt < 4; nt++)
            #pragma unroll
            for (int i = 0; i < 4; i++) acc[mt][nt][i] = 0.f;

    mbar_wait(mb0, 0);
    compute_plane(sA0, g_w16, acc, orow, mq, g, t);

    mbar_wait(mb1, 0);
    compute_plane(sA1, g_w16 + 8, acc, orow, mq, g, t);

    // ---- epilogue (oh0 clamped: oy always <= 221)
    const int oy = oh0 + orow;
    #pragma unroll
    for (int nt = 0; nt < 4; ++nt) {
        const int co0 = nt * 8 + t * 2;
        const float bs0 = __ldg(&bias[co0]);
        const float bs1 = __ldg(&bias[co0 + 1]);
        float* o0 = out + (((size_t)b * CO_ + co0)     * OH_ + oy) * OW_;
        float* o1 = out + (((size_t)b * CO_ + co0 + 1) * OH_ + oy) * OW_;
        #pragma unroll
        for (int mt = 0; mt < 4; ++mt) {
            const int pl = px0 + mq * 64 + mt * 16 + g;
            o0[pl]     = acc[mt][nt][0] + bs0;
            o1[pl]     = acc[mt][nt][1] + bs1;
            o0[pl + 8] = acc[mt][nt][2] + bs0;
            o1[pl + 8] = acc[mt][nt][3] + bs1;
        }
    }
}

extern "C" void kernel_launch(void* const* d_in, const int* in_sizes, int n_in,
                              void* d_out, int out_size)
{
    const float* x    = (const float*)d_in[0];
    const float* w    = (const float*)d_in[1];
    const float* bias = (const float*)d_in[2];
    float* out        = (float*)d_out;

    cvt_xw<<<XBLOCKS + 1, 256>>>(x, w);

    cudaFuncSetAttribute(conv3x3_mma,
                         cudaFuncAttributeMaxDynamicSharedMemorySize, SMEM_BYTES);
    conv3x3_mma<<<B_ * YT * XT, THREADS, SMEM_BYTES>>>(bias, out);
}